// round 17
// baseline (speedup 1.0000x reference)
#include <cuda_runtime.h>
#include <cuda_fp16.h>
#include <math.h>

#define Bz 4
#define Nn 4096
#define Cin 128
#define Cout 128
#define Kk 10
#define Ll 50
#define Ne 65536
#define TBtot (Ll * Bz)   // 200
#define RNN_BLOCKS 128
#define RNN_THREADS 512
#define NBAR 16           // tree-barrier counters (8 arrivals each)

// smem layout for k_rnn_mma (bytes)
#define WS_STRIDE 4112                  // 4096 + 16 pad
#define SM_WS (32 * WS_STRIDE)          // 131584
#define SM_BW (16 * 2048)               // 32768: warp-private B strips (8 rows x 256 B)
#define SM_DP (16 * 32 * 8 * 4)         // 16384 (aliased as Wih_s in prologue)
#define SM_GI (TBtot * 32 * 4)          // 25600: gih slice [tb][row]
#define SM_RNN (SM_WS + SM_BW + SM_DP + SM_GI)   // 206336

// ---------------- scratch (static device globals; no allocs) ----------------
__device__ __align__(16) float  g_filt[2 * Bz * Nn * Cout];  // 16 MB
__device__ __align__(16) float  g_y[2][Bz * Nn * Cout];      // 16 MB
__device__ __align__(16) float  g_res[Bz * Nn * Cout];       // 8 MB
__device__ __align__(16) float  g_res2[Bz * Nn * Kk];        // gelu(res@dW^T+db)
__device__ __align__(16) signed char g_hq[2 * 4 * Nn];       // ping-pong h int8 [buf][b][node]
__device__ __align__(16) float  g_hf[4 * Nn];                // final h fp32 [b][node]
__device__ __align__(256) unsigned int g_bars[NBAR][64];     // counters 256 B apart

// ---------------- helpers ----------------
__device__ __forceinline__ float gelu_exact(float x) {
    return 0.5f * x * (1.0f + erff(x * 0.7071067811865476f));
}

__device__ __forceinline__ float tanh_fast(float x) {
    float e = __expf(2.0f * x);
    return 1.0f - __fdividef(2.0f, e + 1.0f);
}

__device__ __forceinline__ float2 ffma2(float2 a, float2 b, float2 c) {
    unsigned long long au = *reinterpret_cast<unsigned long long*>(&a);
    unsigned long long bu = *reinterpret_cast<unsigned long long*>(&b);
    unsigned long long cu = *reinterpret_cast<unsigned long long*>(&c);
    unsigned long long du;
    asm("fma.rn.f32x2 %0, %1, %2, %3;" : "=l"(du) : "l"(au), "l"(bu), "l"(cu));
    return *reinterpret_cast<float2*>(&du);
}

__device__ __forceinline__ uint4 ldcg_u4(const uint4* p) {
    uint4 v;
    asm volatile("ld.global.cg.v4.u32 {%0,%1,%2,%3}, [%4];"
                 : "=r"(v.x), "=r"(v.y), "=r"(v.z), "=r"(v.w) : "l"(p));
    return v;
}

__device__ __forceinline__ unsigned int ld_acq(const unsigned int* p) {
    unsigned int v;
    asm volatile("ld.acquire.gpu.global.u32 %0, [%1];" : "=r"(v) : "l"(p));
    return v;
}

__device__ __forceinline__ void red_release_add(unsigned int* p, unsigned int v) {
    asm volatile("red.release.gpu.global.add.u32 [%0], %1;" :: "l"(p), "r"(v) : "memory");
}

__device__ __forceinline__ void mma_s8(int* d,
                                       unsigned int a0, unsigned int a1,
                                       unsigned int a2, unsigned int a3,
                                       unsigned int b0, unsigned int b1) {
    asm volatile(
        "mma.sync.aligned.m16n8k32.row.col.s32.s8.s8.s32 "
        "{%0,%1,%2,%3}, {%4,%5,%6,%7}, {%8,%9}, {%0,%1,%2,%3};"
        : "+r"(d[0]), "+r"(d[1]), "+r"(d[2]), "+r"(d[3])
        : "r"(a0), "r"(a1), "r"(a2), "r"(a3), "r"(b0), "r"(b1));
}

__device__ __forceinline__ int q8(float v, float s) {
    int x = __float2int_rn(v * s);
    return max(-127, min(127, x));
}

// ---------------- reset barrier counters (1 block) ----------------
__global__ void k_reset() {
    if (threadIdx.x < NBAR) g_bars[threadIdx.x][0] = 0u;
}

// ---------------- zero kernel: g_y (both) + g_res ----------------
__global__ void k_zero_all() {
    int i = blockIdx.x * blockDim.x + threadIdx.x;   // 1,048,576 threads
    float4 z = make_float4(0.f, 0.f, 0.f, 0.f);
    ((float4*)g_y)[i] = z;
    if (i < Bz * Nn * Cout / 4) ((float4*)g_res)[i] = z;
}

// ---------------- filt = fea @ W_l : 8 rows/warp register blocking ----------------
__global__ void k_gemm_filt(const float* __restrict__ fea,
                            const float* __restrict__ W1,
                            const float* __restrict__ W2) {
    extern __shared__ float4 Ws[];  // [128 c][32 lane-f4] = 64 KB
    const float4* W = (const float4*)(blockIdx.y ? W2 : W1);
    for (int i = threadIdx.x; i < Cin * Cout / 4; i += blockDim.x) Ws[i] = W[i];
    __syncthreads();

    int warp = threadIdx.x >> 5, lane = threadIdx.x & 31;
    int rowbase = (blockIdx.x * 8 + warp) * 8;
    const float4* f4 = (const float4*)fea + (size_t)rowbase * (Cin / 4);

    float2 acc[8][2];
#pragma unroll
    for (int r = 0; r < 8; r++) { acc[r][0] = make_float2(0.f, 0.f); acc[r][1] = make_float2(0.f, 0.f); }

    for (int c4 = 0; c4 < Cin / 4; c4++) {
        float4 fv[8];
#pragma unroll
        for (int r = 0; r < 8; r++) fv[r] = __ldg(f4 + r * (Cin / 4) + c4);
#pragma unroll
        for (int j = 0; j < 4; j++) {
            float4 w = Ws[(c4 * 4 + j) * 32 + lane];
            float2 wlo = make_float2(w.x, w.y), whi = make_float2(w.z, w.w);
#pragma unroll
            for (int r = 0; r < 8; r++) {
                float s = (j == 0) ? fv[r].x : (j == 1) ? fv[r].y : (j == 2) ? fv[r].z : fv[r].w;
                float2 ss = make_float2(s, s);
                acc[r][0] = ffma2(ss, wlo, acc[r][0]);
                acc[r][1] = ffma2(ss, whi, acc[r][1]);
            }
        }
    }

    float* out = g_filt + (size_t)blockIdx.y * Bz * Nn * Cout;
#pragma unroll
    for (int r = 0; r < 8; r++) {
        float4 o = make_float4(acc[r][0].x, acc[r][0].y, acc[r][1].x, acc[r][1].y);
        ((float4*)(out + (size_t)(rowbase + r) * Cout))[lane] = o;
    }
}

// ---------------- merged COO spmm: both layers, one-shot blocks ----------------
__global__ void k_spmm2(const int* __restrict__ idx0, const float* __restrict__ val0,
                        const int* __restrict__ idx1, const float* __restrict__ val1,
                        const float* __restrict__ d0, const float* __restrict__ d1,
                        int pass) {
    int g = blockIdx.x * blockDim.x + threadIdx.x;
    int w = g >> 5, lane = g & 31;           // w in [0, 2*Bz*Ne)
    int l = w >> 18;                          // Bz*Ne = 2^18
    int b = (w >> 16) & 3;
    int e = w & (Ne - 1);

    const int* idx = l ? idx1 : idx0;
    const float* val = l ? val1 : val0;
    const int* ib = idx + (size_t)b * 2 * Ne;
    int r = ib[e];
    int c = ib[Ne + e];
    float v = val[(size_t)b * Ne + e];

    const float* X;
    float* Y;
    if (pass == 0) {
        X = g_filt + (size_t)l * Bz * Nn * Cout;
        Y = g_y[l];
    } else {
        v *= __ldg((l ? d1 : d0) + c);
        X = g_y[l];
        Y = g_res;
    }
    float4 xv = ((const float4*)(X + ((size_t)b * Nn + c) * Cout))[lane];
    float4 add = make_float4(v * xv.x, v * xv.y, v * xv.z, v * xv.w);
    atomicAdd(((float4*)(Y + ((size_t)b * Nn + r) * Cout)) + lane, add);
}

// ---------------- persistent RNN: int8 MMA, fused gih, warp-private B, tree barrier ----------------
__global__ void __launch_bounds__(RNN_THREADS, 1) k_rnn_mma(
    const float* __restrict__ Whh,
    const int* __restrict__ joblst,
    const float* __restrict__ item_emb,
    const float* __restrict__ W_ih,
    const float* __restrict__ b_ih,
    const float* __restrict__ b_hh) {
    extern __shared__ unsigned char smraw[];
    unsigned char* Ws = smraw;                            // [32][WS_STRIDE] s8
    unsigned char* Bw = smraw + SM_WS;                    // [16 warp][2048] s8 (8 rows x 256B)
    int* Dp = (int*)(smraw + SM_WS + SM_BW);              // [16 warp][256] s32 (prologue: Wih_s)
    float* Wih_s = (float*)Dp;                            // [128 c][32 row] f32 (prologue alias)
    float* gi_s = (float*)(smraw + SM_WS + SM_BW + SM_DP); // [200 tb][32 row] f32

    int tid = threadIdx.x, warp = tid >> 5, lane = tid & 31;
    int row0 = blockIdx.x * 32;
    int g = lane >> 2, q = lane & 3;

    // ---- prologue 1: zero B strips; quantize W slice; stage W_ih^T ----
    for (int i = tid; i < SM_BW / 16; i += RNN_THREADS)
        ((uint4*)Bw)[i] = make_uint4(0u, 0u, 0u, 0u);
    for (int idx = tid; idx < 32 * 1024; idx += RNN_THREADS) {
        int r = idx >> 10, c4 = idx & 1023;
        float4 w = __ldg((const float4*)Whh + (size_t)(row0 + r) * (Nn / 4) + c4);
        int q0 = q8(w.x, 8192.f), q1 = q8(w.y, 8192.f);
        int q2 = q8(w.z, 8192.f), q3 = q8(w.w, 8192.f);
        ((unsigned int*)Ws)[r * (WS_STRIDE / 4) + c4] =
            (q0 & 255) | ((q1 & 255) << 8) | ((q2 & 255) << 16) | ((q3 & 255) << 24);
    }
    // Wih_s[c][row] = W_ih[row0+row][c]
    for (int idx = tid; idx < 32 * Cin; idx += RNN_THREADS) {
        int r = idx >> 7, c = idx & 127;
        Wih_s[c * 32 + r] = __ldg(W_ih + (size_t)(row0 + r) * Cin + c);
    }
    __syncthreads();

    // ---- prologue 2: gih slice gi_s[tb][row], tb = t*4+b ----
    for (int v = tid; v < TBtot * 32; v += RNN_THREADS) {
        int tb = v >> 5, row = lane;      // v&31 == lane (v ≡ tid mod 512)
        int t = tb >> 2, b = tb & 3;
        int j = __ldg(joblst + b * Ll + t);
        float acc = __ldg(b_ih + row0 + row) + __ldg(b_hh + row0 + row);
        const float4* e4 = (const float4*)(item_emb + (size_t)j * Cout);
#pragma unroll 8
        for (int c4 = 0; c4 < 32; c4++) {
            float4 e = __ldg(e4 + c4);
            const float* wp = Wih_s + (c4 * 4) * 32 + row;
            acc = fmaf(e.x, wp[0], acc);
            acc = fmaf(e.y, wp[32], acc);
            acc = fmaf(e.z, wp[64], acc);
            acc = fmaf(e.w, wp[96], acc);
        }
        gi_s[v] = acc;
    }
    __syncthreads();   // gi_s done; Dp area now free for MMA partials

    const float inv_scale = 1.f / (8192.f * 127.f);
    int myrow = tid >> 2, myb = tid & 3;   // reduce-phase mapping (tid < 128)
    unsigned int* mybar = &g_bars[blockIdx.x & (NBAR - 1)][0];

    for (int t = 0; t < Ll; t++) {
        float gval = 0.f;
        if (tid < 128) gval = gi_s[(t * 4 + myb) * 32 + myrow];

        if (t > 0) {
            // warp-private B load: 4 rows x 256 B window at node offset warp*256
            const uint4* src = (const uint4*)g_hq + (t & 1) * 1024;  // [b][node/16]
            uint4* bw = (uint4*)(Bw + warp * 2048);
            bw[lane]      = ldcg_u4(src + (lane >> 4) * 256 + warp * 16 + (lane & 15));
            bw[lane + 32] = ldcg_u4(src + ((lane + 32) >> 4) * 256 + warp * 16 + (lane & 15));
            __syncwarp();

            int d0[4] = {0, 0, 0, 0}, d1[4] = {0, 0, 0, 0};
#pragma unroll
            for (int kt = 0; kt < 8; kt++) {
                int ko = warp * 256 + kt * 32 + q * 4;     // global k offset for A
                int kb = kt * 32 + q * 4;                  // local offset in B strip
                unsigned int b0 = *(const unsigned int*)(Bw + warp * 2048 + g * 256 + kb);
                unsigned int b1 = *(const unsigned int*)(Bw + warp * 2048 + g * 256 + kb + 16);
                unsigned int a0 = *(const unsigned int*)(Ws + g * WS_STRIDE + ko);
                unsigned int a1 = *(const unsigned int*)(Ws + (g + 8) * WS_STRIDE + ko);
                unsigned int a2 = *(const unsigned int*)(Ws + g * WS_STRIDE + ko + 16);
                unsigned int a3 = *(const unsigned int*)(Ws + (g + 8) * WS_STRIDE + ko + 16);
                mma_s8(d0, a0, a1, a2, a3, b0, b1);
                unsigned int c0 = *(const unsigned int*)(Ws + (g + 16) * WS_STRIDE + ko);
                unsigned int c1 = *(const unsigned int*)(Ws + (g + 24) * WS_STRIDE + ko);
                unsigned int c2 = *(const unsigned int*)(Ws + (g + 16) * WS_STRIDE + ko + 16);
                unsigned int c3 = *(const unsigned int*)(Ws + (g + 24) * WS_STRIDE + ko + 16);
                mma_s8(d1, c0, c1, c2, c3, b0, b1);
            }
            int* dpw = Dp + warp * 256;
            dpw[g * 8 + 2 * q] = d0[0];        dpw[g * 8 + 2 * q + 1] = d0[1];
            dpw[(g + 8) * 8 + 2 * q] = d0[2];  dpw[(g + 8) * 8 + 2 * q + 1] = d0[3];
            dpw[(g + 16) * 8 + 2 * q] = d1[0]; dpw[(g + 16) * 8 + 2 * q + 1] = d1[1];
            dpw[(g + 24) * 8 + 2 * q] = d1[2]; dpw[(g + 24) * 8 + 2 * q + 1] = d1[3];
        }
        __syncthreads();

        // reduce + in-register word assembly + publish (warps 0-3)
        if (tid < 128) {
            float x = gval;
            if (t > 0) {
                int s = 0;
#pragma unroll
                for (int w = 0; w < 16; w++) s += Dp[w * 256 + myrow * 8 + myb];
                x += (float)s * inv_scale;
            }
            float h = tanh_fast(x);
            if (t == Ll - 1) {
                g_hf[myb * Nn + row0 + myrow] = h;
            } else {
                unsigned int ub = (unsigned int)(unsigned char)(signed char)__float2int_rn(h * 127.f);
                int srcbase = lane & 0x13;                      // 16j + b
                unsigned int w0 = __shfl_sync(0xffffffffu, ub, srcbase);
                unsigned int w1 = __shfl_sync(0xffffffffu, ub, srcbase | 4);
                unsigned int w2 = __shfl_sync(0xffffffffu, ub, srcbase | 8);
                unsigned int w3 = __shfl_sync(0xffffffffu, ub, srcbase | 12);
                if ((lane & 0x0C) == 0) {                       // 8 writer lanes/warp
                    unsigned int word = w0 | (w1 << 8) | (w2 << 16) | (w3 << 24);
                    int b = lane & 3, j = (lane >> 4) & 1;
                    int node = row0 + warp * 8 + 4 * j;
                    *(unsigned int*)(g_hq + ((t + 1) & 1) * 4 * Nn + b * Nn + node) = word;
                }
            }
        }

        if (t < Ll - 1) {
            __syncthreads();
            if (warp == 0) {
                if (lane == 0) red_release_add(mybar, 1u);
                unsigned int target = (unsigned int)(RNN_BLOCKS / NBAR) * (t + 1);
                if (lane < NBAR) {
                    const unsigned int* cp = &g_bars[lane][0];
                    while (ld_acq(cp) < target) { }
                }
            }
            __syncthreads();
        }
    }
}

// ---------------- epilogue stage 1 (no h): g_res2 = gelu(res @ dW^T + db) ----------------
__global__ void k_epi1(const float* __restrict__ dW, const float* __restrict__ db) {
    __shared__ float dWs[Kk * Cout];
    __shared__ float dbs[Kk];
    for (int i = threadIdx.x; i < Kk * Cout; i += blockDim.x) dWs[i] = dW[i];
    if (threadIdx.x < Kk) dbs[threadIdx.x] = db[threadIdx.x];
    __syncthreads();

    int warp = threadIdx.x >> 5, lane = threadIdx.x & 31;
    int gw = blockIdx.x * (blockDim.x >> 5) + warp;  // = b*Nn + n
    if (gw >= Bz * Nn) return;

    float4 r = ((const float4*)(g_res + (size_t)gw * Cout))[lane];

#pragma unroll
    for (int k = 0; k < Kk; k++) {
        const float4* w4 = (const float4*)(dWs + k * Cout);
        float4 w = w4[lane];
        float p = r.x * w.x + r.y * w.y + r.z * w.z + r.w * w.w;
#pragma unroll
        for (int off = 16; off; off >>= 1) p += __shfl_xor_sync(0xffffffffu, p, off);
        if (lane == 0) g_res2[(size_t)gw * Kk + k] = gelu_exact(p + dbs[k]);
    }
}

// ---------------- epilogue stage 2 (tiny): out = sigmoid(res2 * gelu(h)) ----------------
__global__ void k_epi2(float* __restrict__ out) {
    int i = blockIdx.x * blockDim.x + threadIdx.x;   // Bz*Nn threads
    float eh = gelu_exact(g_hf[i]);                  // [b][n] == gw order
#pragma unroll
    for (int k = 0; k < Kk; k++) {
        float v = g_res2[(size_t)i * Kk + k] * eh;
        out[(size_t)i * Kk + k] = 1.0f / (1.0f + expf(-v));
    }
}

// ---------------- launch ----------------
extern "C" void kernel_launch(void* const* d_in, const int* in_sizes, int n_in,
                              void* d_out, int out_size) {
    const int*   phi1_idx     = (const int*)d_in[0];
    const float* phi1_val     = (const float*)d_in[1];
    const int*   phi1_inv_idx = (const int*)d_in[2];
    const float* phi1_inv_val = (const float*)d_in[3];
    const int*   phi2_idx     = (const int*)d_in[4];
    const float* phi2_val     = (const float*)d_in[5];
    const int*   phi2_inv_idx = (const int*)d_in[6];
    const float* phi2_inv_val = (const float*)d_in[7];
    const float* fea          = (const float*)d_in[8];
    const int*   joblst       = (const int*)d_in[9];
    const float* W1           = (const float*)d_in[10];
    const float* d1           = (const float*)d_in[11];
    const float* W2           = (const float*)d_in[12];
    const float* d2           = (const float*)d_in[13];
    const float* W_ih         = (const float*)d_in[14];
    const float* W_hh         = (const float*)d_in[15];
    const float* b_ih         = (const float*)d_in[16];
    const float* b_hh         = (const float*)d_in[17];
    const float* dense_W      = (const float*)d_in[18];
    const float* dense_b      = (const float*)d_in[19];
    const float* item_emb     = (const float*)d_in[20];
    float*       out          = (float*)d_out;

    static cudaStream_t s2 = nullptr;
    static cudaEvent_t ev0 = nullptr, ev2 = nullptr;
    if (!s2) {
        cudaStreamCreateWithFlags(&s2, cudaStreamNonBlocking);
        cudaEventCreateWithFlags(&ev0, cudaEventDisableTiming);
        cudaEventCreateWithFlags(&ev2, cudaEventDisableTiming);
        cudaFuncSetAttribute(k_gemm_filt, cudaFuncAttributeMaxDynamicSharedMemorySize, 65536);
        cudaFuncSetAttribute(k_rnn_mma, cudaFuncAttributeMaxDynamicSharedMemorySize, SM_RNN);
    }

    // fork point
    cudaEventRecord(ev0, 0);
    cudaStreamWaitEvent(s2, ev0, 0);

    // ---- s2: conv chain (zero -> gemm -> spmm x2 -> epi stage 1) ----
    k_zero_all<<<4096, 256, 0, s2>>>();
    k_gemm_filt<<<dim3(256, 2), 256, 65536, s2>>>(fea, W1, W2);
    k_spmm2<<<65536, 256, 0, s2>>>(phi1_inv_idx, phi1_inv_val, phi2_inv_idx, phi2_inv_val,
                                   nullptr, nullptr, 0);
    k_spmm2<<<65536, 256, 0, s2>>>(phi1_idx, phi1_val, phi2_idx, phi2_val, d1, d2, 1);
    k_epi1<<<(Bz * Nn) / 8, 256, 0, s2>>>(dense_W, dense_b);
    cudaEventRecord(ev2, s2);

    // ---- main: reset counters, persistent RNN (gih fused in prologue) ----
    k_reset<<<1, 32>>>();
    k_rnn_mma<<<RNN_BLOCKS, RNN_THREADS, SM_RNN>>>(W_hh, joblst, item_emb, W_ih, b_ih, b_hh);

    // ---- join + tiny final epilogue ----
    cudaStreamWaitEvent(0, ev2, 0);
    k_epi2<<<(Bz * Nn) / 256, 256>>>(out);
}